// round 1
// baseline (speedup 1.0000x reference)
#include <cuda_runtime.h>
#include <cstdint>

// Problem constants (fixed by the dataset)
#define B_  8
#define S_  2048
#define DV_ 768
#define DA_ 512
#define K_  512
#define M_  (B_*S_)   // 16384

// Scratch (alloc-guard-safe __device__ globals)
__device__ float  g_sm_v[M_*DV_];      // smoothed vision  (for audio energy's cross term)
__device__ float  g_sm_a[M_*DA_];      // smoothed audio   (for vision energy's cross term)
__device__ float  g_peff_v[K_*DA_];    // proto_vision @ proj_audio_to_vision  -> (K, DA)
__device__ float  g_peff_a[K_*DV_];    // proto_audio  @ proj_vision_to_audio  -> (K, DV)
__device__ double g_acc;

__global__ void zero_acc_k() { g_acc = 0.0; }

// Window-3 temporal mean with edge truncation, vectorized float4 along D.
__global__ void smooth3_k(const float4* __restrict__ f, float4* __restrict__ o,
                          int S, int D4, int total)
{
    int idx = blockIdx.x * blockDim.x + threadIdx.x;
    if (idx >= total) return;
    int t = (idx / D4) % S;
    float4 c = f[idx];
    float sx = c.x, sy = c.y, sz = c.z, sw = c.w;
    float cnt = 1.f;
    if (t > 0)     { float4 p = f[idx - D4]; sx += p.x; sy += p.y; sz += p.z; sw += p.w; cnt += 1.f; }
    if (t < S - 1) { float4 n = f[idx + D4]; sx += n.x; sy += n.y; sz += n.z; sw += n.w; cnt += 1.f; }
    float inv = 1.f / cnt;
    o[idx] = make_float4(sx * inv, sy * inv, sz * inv, sw * inv);
}

// Small NN GEMM: O[m][n] = sum_k A[m][k] * W[k][n].  Dims multiples of 32.
__global__ void gemm_nn_k(const float* __restrict__ A, const float* __restrict__ W,
                          float* __restrict__ O, int Ng, int Kg)
{
    __shared__ float As[32][33];
    __shared__ float Ws[32][33];
    int tx = threadIdx.x, ty = threadIdx.y;
    int row = blockIdx.y * 32 + ty;
    int col = blockIdx.x * 32 + tx;
    float acc = 0.f;
    for (int kt = 0; kt < Kg; kt += 32) {
        As[ty][tx] = A[row * Kg + kt + tx];
        Ws[ty][tx] = W[(kt + ty) * Ng + col];
        __syncthreads();
#pragma unroll
        for (int kk = 0; kk < 32; kk++) acc += As[ty][kk] * Ws[kk][tx];
        __syncthreads();
    }
    O[row * Ng + col] = acc;
}

// One GEMM phase of the fused kernel: acc[8][4] += A_tile(128 x D) * B_tile(64 x D)^T
// A: (M, D) row-major, B: (K, D) row-major.  D multiple of 16.
__device__ __forceinline__ void gemm_phase(const float* __restrict__ A,
                                           const float* __restrict__ Bm,
                                           int D, int rowBase, int colBase, int tid,
                                           float acc[8][4],
                                           float (*As)[132], float (*Bs)[68])
{
    const int ty = tid >> 4;   // 0..15 -> 8 rows each
    const int tx = tid & 15;   // 0..15 -> 4 cols each
    const int nt = D >> 4;
    for (int t = 0; t < nt; ++t) {
        __syncthreads();
#pragma unroll
        for (int i = 0; i < 8; ++i) {          // 128x16 A tile, transposed into smem
            int idx = tid + i * 256;
            int r = idx >> 4, d = idx & 15;
            As[d][r] = A[(rowBase + r) * D + t * 16 + d];
        }
#pragma unroll
        for (int i = 0; i < 4; ++i) {          // 64x16 B tile
            int idx = tid + i * 256;
            int r = idx >> 4, d = idx & 15;
            Bs[d][r] = Bm[(colBase + r) * D + t * 16 + d];
        }
        __syncthreads();
#pragma unroll
        for (int dd = 0; dd < 16; ++dd) {
            float4 a0 = *reinterpret_cast<const float4*>(&As[dd][ty * 8]);
            float4 a1 = *reinterpret_cast<const float4*>(&As[dd][ty * 8 + 4]);
            float4 b  = *reinterpret_cast<const float4*>(&Bs[dd][tx * 4]);
            float av[8] = {a0.x, a0.y, a0.z, a0.w, a1.x, a1.y, a1.z, a1.w};
            float bv[4] = {b.x, b.y, b.z, b.w};
#pragma unroll
            for (int i = 0; i < 8; ++i)
#pragma unroll
                for (int j = 0; j < 4; ++j)
                    acc[i][j] += av[i] * bv[j];
        }
    }
}

// Fused dual-GEMM + softplus-energy reduction.
//   intra = A1(row) . B1(col)   over D1
//   cross = A2(row) . B2(col)   over D2
//   sal = 0.3*cross^2 + 0.7*intra^2 ; accumulate softplus(sal*intra)
__global__ __launch_bounds__(256, 2) void fused_energy_k(
    const float* __restrict__ A1, const float* __restrict__ B1, int D1,
    const float* __restrict__ A2, const float* __restrict__ B2, int D2)
{
    __shared__ float As[16][132];
    __shared__ float Bs[16][68];
    __shared__ float warpsum[8];

    const int tid = threadIdx.x;
    const int rowBase = blockIdx.y * 128;
    const int colBase = blockIdx.x * 64;

    float acc1[8][4], acc2[8][4];
#pragma unroll
    for (int i = 0; i < 8; ++i)
#pragma unroll
        for (int j = 0; j < 4; ++j) { acc1[i][j] = 0.f; acc2[i][j] = 0.f; }

    gemm_phase(A1, B1, D1, rowBase, colBase, tid, acc1, As, Bs);
    gemm_phase(A2, B2, D2, rowBase, colBase, tid, acc2, As, Bs);

    // epilogue: softplus(saliency * intra), summed
    float local = 0.f;
#pragma unroll
    for (int i = 0; i < 8; ++i) {
#pragma unroll
        for (int j = 0; j < 4; ++j) {
            float x = acc1[i][j];          // intra
            float c = acc2[i][j];          // cross
            float sal = 0.3f * c * c + 0.7f * x * x;
            float z = sal * x;
            float sp = fmaxf(z, 0.f) + __logf(1.f + __expf(-fabsf(z)));
            local += sp;
        }
    }

    // block reduce -> double atomic
#pragma unroll
    for (int off = 16; off; off >>= 1)
        local += __shfl_xor_sync(0xffffffffu, local, off);
    if ((tid & 31) == 0) warpsum[tid >> 5] = local;
    __syncthreads();
    if (tid < 8) {
        float v = warpsum[tid];
#pragma unroll
        for (int off = 4; off; off >>= 1)
            v += __shfl_xor_sync(0xffu, v, off);
        if (tid == 0) atomicAdd(&g_acc, (double)v);
    }
}

__global__ void final_k(float* __restrict__ out)
{
    out[0] = (float)(-g_acc);
}

extern "C" void kernel_launch(void* const* d_in, const int* in_sizes, int n_in,
                              void* d_out, int out_size)
{
    const float* fv  = (const float*)d_in[0];  // (B,S,DV)
    const float* fa  = (const float*)d_in[1];  // (B,S,DA)
    const float* pv  = (const float*)d_in[2];  // (K,DV)
    const float* pa  = (const float*)d_in[3];  // (K,DA)
    const float* Wav = (const float*)d_in[4];  // (DV,DA)  audio->vision
    const float* Wva = (const float*)d_in[5];  // (DA,DV)  vision->audio
    float* out = (float*)d_out;

    float *smv, *sma, *pev, *pea;
    cudaGetSymbolAddress((void**)&smv, g_sm_v);
    cudaGetSymbolAddress((void**)&sma, g_sm_a);
    cudaGetSymbolAddress((void**)&pev, g_peff_v);
    cudaGetSymbolAddress((void**)&pea, g_peff_a);

    zero_acc_k<<<1, 1>>>();

    {
        int tot = M_ * (DV_ / 4);
        smooth3_k<<<(tot + 255) / 256, 256>>>((const float4*)fv, (float4*)smv, S_, DV_ / 4, tot);
    }
    {
        int tot = M_ * (DA_ / 4);
        smooth3_k<<<(tot + 255) / 256, 256>>>((const float4*)fa, (float4*)sma, S_, DA_ / 4, tot);
    }

    // P_eff_v (K,DA) = proto_vision (K,DV) @ Wav (DV,DA)
    gemm_nn_k<<<dim3(DA_ / 32, K_ / 32), dim3(32, 32)>>>(pv, Wav, pev, DA_, DV_);
    // P_eff_a (K,DV) = proto_audio (K,DA) @ Wva (DA,DV)
    gemm_nn_k<<<dim3(DV_ / 32, K_ / 32), dim3(32, 32)>>>(pa, Wva, pea, DV_, DA_);

    dim3 grid(K_ / 64, M_ / 128);
    // vision energy: intra = fv . proto_v (D=768), cross = smooth(fa) . P_eff_v (D=512)
    fused_energy_k<<<grid, 256>>>(fv, pv, DV_, sma, pev, DA_);
    // audio energy:  intra = fa . proto_a (D=512), cross = smooth(fv) . P_eff_a (D=768)
    fused_energy_k<<<grid, 256>>>(fa, pa, DA_, smv, pea, DV_);

    final_k<<<1, 1>>>(out);
}

// round 2
// speedup vs baseline: 1.0017x; 1.0017x over previous
#include <cuda_runtime.h>
#include <cstdint>

// Problem constants (fixed by the dataset)
#define B_  8
#define S_  2048
#define DV_ 768
#define DA_ 512
#define K_  512
#define M_  (B_*S_)   // 16384

// Scratch (alloc-guard-safe __device__ globals)
__device__ float  g_sm_v[M_*DV_];      // smoothed vision  (for audio energy's cross term)
__device__ float  g_sm_a[M_*DA_];      // smoothed audio   (for vision energy's cross term)
__device__ float  g_peff_v[K_*DA_];    // proto_vision @ proj_audio_to_vision  -> (K, DA)
__device__ float  g_peff_a[K_*DV_];    // proto_audio  @ proj_vision_to_audio  -> (K, DV)
__device__ double g_acc;

__global__ void zero_acc_k() { g_acc = 0.0; }

// Window-3 temporal mean with edge truncation, vectorized float4 along D.
__global__ void smooth3_k(const float4* __restrict__ f, float4* __restrict__ o,
                          int S, int D4, int total)
{
    int idx = blockIdx.x * blockDim.x + threadIdx.x;
    if (idx >= total) return;
    int t = (idx / D4) % S;
    float4 c = f[idx];
    float sx = c.x, sy = c.y, sz = c.z, sw = c.w;
    float cnt = 1.f;
    if (t > 0)     { float4 p = f[idx - D4]; sx += p.x; sy += p.y; sz += p.z; sw += p.w; cnt += 1.f; }
    if (t < S - 1) { float4 n = f[idx + D4]; sx += n.x; sy += n.y; sz += n.z; sw += n.w; cnt += 1.f; }
    float inv = 1.f / cnt;
    o[idx] = make_float4(sx * inv, sy * inv, sz * inv, sw * inv);
}

// Small NN GEMM: O[m][n] = sum_k A[m][k] * W[k][n].  Dims multiples of 32.
__global__ void gemm_nn_k(const float* __restrict__ A, const float* __restrict__ W,
                          float* __restrict__ O, int Ng, int Kg)
{
    __shared__ float As[32][33];
    __shared__ float Ws[32][33];
    int tx = threadIdx.x, ty = threadIdx.y;
    int row = blockIdx.y * 32 + ty;
    int col = blockIdx.x * 32 + tx;
    float acc = 0.f;
    for (int kt = 0; kt < Kg; kt += 32) {
        As[ty][tx] = A[row * Kg + kt + tx];
        Ws[ty][tx] = W[(kt + ty) * Ng + col];
        __syncthreads();
#pragma unroll
        for (int kk = 0; kk < 32; kk++) acc += As[ty][kk] * Ws[kk][tx];
        __syncthreads();
    }
    O[row * Ng + col] = acc;
}

// One GEMM phase of the fused kernel: acc[8][4] += A_tile(128 x D) * B_tile(64 x D)^T
// A: (M, D) row-major, B: (K, D) row-major.  D multiple of 16.
__device__ __forceinline__ void gemm_phase(const float* __restrict__ A,
                                           const float* __restrict__ Bm,
                                           int D, int rowBase, int colBase, int tid,
                                           float acc[8][4],
                                           float (*As)[132], float (*Bs)[68])
{
    const int ty = tid >> 4;   // 0..15 -> 8 rows each
    const int tx = tid & 15;   // 0..15 -> 4 cols each
    const int nt = D >> 4;
    for (int t = 0; t < nt; ++t) {
        __syncthreads();
#pragma unroll
        for (int i = 0; i < 8; ++i) {          // 128x16 A tile, transposed into smem
            int idx = tid + i * 256;
            int r = idx >> 4, d = idx & 15;
            As[d][r] = A[(rowBase + r) * D + t * 16 + d];
        }
#pragma unroll
        for (int i = 0; i < 4; ++i) {          // 64x16 B tile
            int idx = tid + i * 256;
            int r = idx >> 4, d = idx & 15;
            Bs[d][r] = Bm[(colBase + r) * D + t * 16 + d];
        }
        __syncthreads();
#pragma unroll
        for (int dd = 0; dd < 16; ++dd) {
            float4 a0 = *reinterpret_cast<const float4*>(&As[dd][ty * 8]);
            float4 a1 = *reinterpret_cast<const float4*>(&As[dd][ty * 8 + 4]);
            float4 b  = *reinterpret_cast<const float4*>(&Bs[dd][tx * 4]);
            float av[8] = {a0.x, a0.y, a0.z, a0.w, a1.x, a1.y, a1.z, a1.w};
            float bv[4] = {b.x, b.y, b.z, b.w};
#pragma unroll
            for (int i = 0; i < 8; ++i)
#pragma unroll
                for (int j = 0; j < 4; ++j)
                    acc[i][j] += av[i] * bv[j];
        }
    }
}

// Fused dual-GEMM + softplus-energy reduction.
//   intra = A1(row) . B1(col)   over D1
//   cross = A2(row) . B2(col)   over D2
//   sal = 0.3*cross^2 + 0.7*intra^2 ; accumulate softplus(sal*intra)
__global__ __launch_bounds__(256, 2) void fused_energy_k(
    const float* __restrict__ A1, const float* __restrict__ B1, int D1,
    const float* __restrict__ A2, const float* __restrict__ B2, int D2)
{
    __shared__ float As[16][132];
    __shared__ float Bs[16][68];
    __shared__ float warpsum[8];

    const int tid = threadIdx.x;
    const int rowBase = blockIdx.y * 128;
    const int colBase = blockIdx.x * 64;

    float acc1[8][4], acc2[8][4];
#pragma unroll
    for (int i = 0; i < 8; ++i)
#pragma unroll
        for (int j = 0; j < 4; ++j) { acc1[i][j] = 0.f; acc2[i][j] = 0.f; }

    gemm_phase(A1, B1, D1, rowBase, colBase, tid, acc1, As, Bs);
    gemm_phase(A2, B2, D2, rowBase, colBase, tid, acc2, As, Bs);

    // epilogue: softplus(saliency * intra), summed
    float local = 0.f;
#pragma unroll
    for (int i = 0; i < 8; ++i) {
#pragma unroll
        for (int j = 0; j < 4; ++j) {
            float x = acc1[i][j];          // intra
            float c = acc2[i][j];          // cross
            float sal = 0.3f * c * c + 0.7f * x * x;
            float z = sal * x;
            float sp = fmaxf(z, 0.f) + __logf(1.f + __expf(-fabsf(z)));
            local += sp;
        }
    }

    // block reduce -> double atomic
#pragma unroll
    for (int off = 16; off; off >>= 1)
        local += __shfl_xor_sync(0xffffffffu, local, off);
    if ((tid & 31) == 0) warpsum[tid >> 5] = local;
    __syncthreads();
    if (tid < 8) {
        float v = warpsum[tid];
#pragma unroll
        for (int off = 4; off; off >>= 1)
            v += __shfl_xor_sync(0xffu, v, off);
        if (tid == 0) atomicAdd(&g_acc, (double)v);
    }
}

__global__ void final_k(float* __restrict__ out)
{
    out[0] = (float)(-g_acc);
}

extern "C" void kernel_launch(void* const* d_in, const int* in_sizes, int n_in,
                              void* d_out, int out_size)
{
    const float* fv  = (const float*)d_in[0];  // (B,S,DV)
    const float* fa  = (const float*)d_in[1];  // (B,S,DA)
    const float* pv  = (const float*)d_in[2];  // (K,DV)
    const float* pa  = (const float*)d_in[3];  // (K,DA)
    const float* Wav = (const float*)d_in[4];  // (DV,DA)  audio->vision
    const float* Wva = (const float*)d_in[5];  // (DA,DV)  vision->audio
    float* out = (float*)d_out;

    float *smv, *sma, *pev, *pea;
    cudaGetSymbolAddress((void**)&smv, g_sm_v);
    cudaGetSymbolAddress((void**)&sma, g_sm_a);
    cudaGetSymbolAddress((void**)&pev, g_peff_v);
    cudaGetSymbolAddress((void**)&pea, g_peff_a);

    zero_acc_k<<<1, 1>>>();

    {
        int tot = M_ * (DV_ / 4);
        smooth3_k<<<(tot + 255) / 256, 256>>>((const float4*)fv, (float4*)smv, S_, DV_ / 4, tot);
    }
    {
        int tot = M_ * (DA_ / 4);
        smooth3_k<<<(tot + 255) / 256, 256>>>((const float4*)fa, (float4*)sma, S_, DA_ / 4, tot);
    }

    // P_eff_v (K,DA) = proto_vision (K,DV) @ Wav (DV,DA)
    gemm_nn_k<<<dim3(DA_ / 32, K_ / 32), dim3(32, 32)>>>(pv, Wav, pev, DA_, DV_);
    // P_eff_a (K,DV) = proto_audio (K,DA) @ Wva (DA,DV)
    gemm_nn_k<<<dim3(DV_ / 32, K_ / 32), dim3(32, 32)>>>(pa, Wva, pea, DV_, DA_);

    dim3 grid(K_ / 64, M_ / 128);
    // vision energy: intra = fv . proto_v (D=768), cross = smooth(fa) . P_eff_v (D=512)
    fused_energy_k<<<grid, 256>>>(fv, pv, DV_, sma, pev, DA_);
    // audio energy:  intra = fa . proto_a (D=512), cross = smooth(fv) . P_eff_a (D=768)
    fused_energy_k<<<grid, 256>>>(fa, pa, DA_, smv, pea, DV_);

    final_k<<<1, 1>>>(out);
}

// round 4
// speedup vs baseline: 2.0980x; 2.0945x over previous
#include <cuda_runtime.h>
#include <cuda_bf16.h>
#include <cstdint>

#define B_  8
#define S_  2048
#define DV_ 768
#define DA_ 512
#define K_  512
#define M_  (B_*S_)   // 16384

typedef __nv_bfloat16 bf16;

#define TILE_M 128
#define TILE_N 128
#define KC 64
#define NST 4
#define PRE 3
#define SMB_OFF (TILE_M*KC*2)                 // 16384
#define ST_BYTES (TILE_M*KC*2 + TILE_N*KC*2)  // 32768
#define DYN_SMEM (NST*ST_BYTES + 256)

// ---- scratch (__device__ globals; alloc-guard-safe) ----
__device__ __align__(1024) bf16 g_fvh[M_*DV_];
__device__ __align__(1024) bf16 g_fvl[M_*DV_];
__device__ __align__(1024) bf16 g_fah[M_*DA_];
__device__ __align__(1024) bf16 g_fal[M_*DA_];
__device__ __align__(1024) bf16 g_svh[M_*DV_];
__device__ __align__(1024) bf16 g_svl[M_*DV_];
__device__ __align__(1024) bf16 g_sah[M_*DA_];
__device__ __align__(1024) bf16 g_sal[M_*DA_];
__device__ __align__(1024) bf16 g_pvh[K_*DV_];
__device__ __align__(1024) bf16 g_pvl[K_*DV_];
__device__ __align__(1024) bf16 g_pah[K_*DA_];
__device__ __align__(1024) bf16 g_pal[K_*DA_];
__device__ __align__(1024) bf16 g_pevh[K_*DA_];
__device__ __align__(1024) bf16 g_pevl[K_*DA_];
__device__ __align__(1024) bf16 g_peah[K_*DV_];
__device__ __align__(1024) bf16 g_peal[K_*DV_];
__device__ double g_acc;

__global__ void zero_acc_k() { g_acc = 0.0; }
__global__ void final_k(float* __restrict__ out) { out[0] = (float)(-g_acc); }

// ---------------- low-level helpers ----------------
__device__ __forceinline__ uint32_t smem_u32(const void* p) {
    uint32_t a;
    asm("{ .reg .u64 t; cvta.to.shared.u64 t, %1; cvt.u32.u64 %0, t; }" : "=r"(a) : "l"(p));
    return a;
}
__device__ __forceinline__ uint32_t swz(uint32_t o) { return o ^ ((o >> 3) & 0x70u); }

__device__ __forceinline__ void cpa16(uint32_t d, const void* s) {
    asm volatile("cp.async.cg.shared.global [%0], [%1], 16;" :: "r"(d), "l"(s));
}
#define CP_COMMIT() asm volatile("cp.async.commit_group;" ::: "memory")
#define CP_WAIT(n)  asm volatile("cp.async.wait_group %0;" :: "n"(n) : "memory")

__device__ __forceinline__ void ldsm4(uint32_t* r, uint32_t addr) {
    asm volatile("ldmatrix.sync.aligned.m8n8.x4.shared.b16 {%0,%1,%2,%3}, [%4];"
        : "=r"(r[0]), "=r"(r[1]), "=r"(r[2]), "=r"(r[3]) : "r"(addr));
}
__device__ __forceinline__ void mma16816(float* d, const uint32_t* a, const uint32_t* b) {
    asm volatile("mma.sync.aligned.m16n8k16.row.col.f32.bf16.bf16.f32 "
        "{%0,%1,%2,%3}, {%4,%5,%6,%7}, {%8,%9}, {%0,%1,%2,%3};"
        : "+f"(d[0]), "+f"(d[1]), "+f"(d[2]), "+f"(d[3])
        : "r"(a[0]), "r"(a[1]), "r"(a[2]), "r"(a[3]), "r"(b[0]), "r"(b[1]));
}

// ---------------- prologue kernels ----------------
__device__ __forceinline__ void split4(float4 v, bf16* __restrict__ H,
                                       bf16* __restrict__ L, size_t idx4) {
    bf16 h0 = __float2bfloat16_rn(v.x), h1 = __float2bfloat16_rn(v.y);
    bf16 h2 = __float2bfloat16_rn(v.z), h3 = __float2bfloat16_rn(v.w);
    bf16 l0 = __float2bfloat16_rn(v.x - __bfloat162float(h0));
    bf16 l1 = __float2bfloat16_rn(v.y - __bfloat162float(h1));
    bf16 l2 = __float2bfloat16_rn(v.z - __bfloat162float(h2));
    bf16 l3 = __float2bfloat16_rn(v.w - __bfloat162float(h3));
    __nv_bfloat162* Hp = reinterpret_cast<__nv_bfloat162*>(H + idx4 * 4);
    __nv_bfloat162* Lp = reinterpret_cast<__nv_bfloat162*>(L + idx4 * 4);
    __nv_bfloat162 t;
    t.x = h0; t.y = h1; Hp[0] = t;  t.x = h2; t.y = h3; Hp[1] = t;
    t.x = l0; t.y = l1; Lp[0] = t;  t.x = l2; t.y = l3; Lp[1] = t;
}

// raw hi/lo split + window-3 temporal mean + split of the smoothed, one pass
__global__ void prep_feat_k(const float4* __restrict__ f,
                            bf16* __restrict__ fh, bf16* __restrict__ fl,
                            bf16* __restrict__ sh, bf16* __restrict__ sl,
                            int D4, int total) {
    int idx = blockIdx.x * blockDim.x + threadIdx.x;
    if (idx >= total) return;
    int t = (idx / D4) % S_;
    float4 c = f[idx];
    float4 sm = c;
    float cnt = 1.f;
    if (t > 0)      { float4 p = f[idx - D4]; sm.x += p.x; sm.y += p.y; sm.z += p.z; sm.w += p.w; cnt += 1.f; }
    if (t < S_ - 1) { float4 n = f[idx + D4]; sm.x += n.x; sm.y += n.y; sm.z += n.z; sm.w += n.w; cnt += 1.f; }
    float inv = 1.f / cnt;
    sm.x *= inv; sm.y *= inv; sm.z *= inv; sm.w *= inv;
    split4(c, fh, fl, idx);
    split4(sm, sh, sl, idx);
}

__global__ void split_k(const float4* __restrict__ x, bf16* __restrict__ h,
                        bf16* __restrict__ l, int n4) {
    int idx = blockIdx.x * blockDim.x + threadIdx.x;
    if (idx >= n4) return;
    split4(x[idx], h, l, idx);
}

// P_eff = A(K_,Kd) @ W(Kd,N) in fp32, output split to bf16 hi/lo
__global__ __launch_bounds__(256) void gemm64_split_k(
    const float* __restrict__ A, const float* __restrict__ W,
    bf16* __restrict__ Oh, bf16* __restrict__ Ol, int N, int Kd) {
    __shared__ float As[16][68];
    __shared__ float Ws[16][68];
    int tid = threadIdx.x;
    int tx = tid & 15, ty = tid >> 4;
    int row0 = blockIdx.y * 64, col0 = blockIdx.x * 64;
    float acc[4][4] = {};
    for (int kt = 0; kt < Kd; kt += 16) {
#pragma unroll
        for (int i = 0; i < 4; i++) {
            int e = tid + i * 256;
            As[e & 15][e >> 4] = A[(size_t)(row0 + (e >> 4)) * Kd + kt + (e & 15)];
        }
#pragma unroll
        for (int i = 0; i < 4; i++) {
            int e = tid + i * 256;
            Ws[e >> 6][e & 63] = W[(size_t)(kt + (e >> 6)) * N + col0 + (e & 63)];
        }
        __syncthreads();
#pragma unroll
        for (int kk = 0; kk < 16; kk++) {
            float a[4], b[4];
#pragma unroll
            for (int i = 0; i < 4; i++) a[i] = As[kk][ty * 4 + i];
#pragma unroll
            for (int j = 0; j < 4; j++) b[j] = Ws[kk][tx * 4 + j];
#pragma unroll
            for (int i = 0; i < 4; i++)
#pragma unroll
                for (int j = 0; j < 4; j++) acc[i][j] += a[i] * b[j];
        }
        __syncthreads();
    }
#pragma unroll
    for (int i = 0; i < 4; i++)
#pragma unroll
        for (int j = 0; j < 4; j++) {
            float x = acc[i][j];
            bf16 h = __float2bfloat16_rn(x);
            size_t o = (size_t)(row0 + ty * 4 + i) * N + col0 + tx * 4 + j;
            Oh[o] = h;
            Ol[o] = __float2bfloat16_rn(x - __bfloat162float(h));
        }
}

// ---------------- fused dual-GEMM (mma.sync) + energy ----------------
struct ChunkArgs { const bf16* A; const bf16* Bp; int D; int c; };

__device__ __forceinline__ ChunkArgs resolve(
    int i, int n1, int C1, int C2,
    const bf16* A1h, const bf16* A1l, const bf16* B1h, const bf16* B1l, int D1,
    const bf16* A2h, const bf16* A2l, const bf16* B2h, const bf16* B2l, int D2) {
    ChunkArgs r;
    int m2 = (i >= n1) ? 1 : 0;
    int j = m2 ? i - n1 : i;
    int C = m2 ? C2 : C1;
    int p = j / C;
    r.c = j - p * C;
    r.D = m2 ? D2 : D1;
    // pass 0: ah*bh   pass 1: ah*bl   pass 2: al*bh
    r.A  = m2 ? (p == 2 ? A2l : A2h) : (p == 2 ? A1l : A1h);
    r.Bp = m2 ? (p == 1 ? B2l : B2h) : (p == 1 ? B1l : B1h);
    return r;
}

__device__ __forceinline__ void load_chunk(uint32_t st, const bf16* Ap, const bf16* Bp,
                                           int D, int rowBase, int colBase, int c, int tid) {
#pragma unroll
    for (int i = 0; i < 4; i++) {
        int e = tid + i * 256;
        int r = e >> 3, cg = e & 7;
        cpa16(st + swz((uint32_t)(r * 128 + cg * 16)),
              Ap + (size_t)(rowBase + r) * D + (c << 6) + cg * 8);
    }
    uint32_t sB = st + SMB_OFF;
#pragma unroll
    for (int i = 0; i < 4; i++) {
        int e = tid + i * 256;
        int r = e >> 3, cg = e & 7;
        cpa16(sB + swz((uint32_t)(r * 128 + cg * 16)),
              Bp + (size_t)(colBase + r) * D + (c << 6) + cg * 8);
    }
}

__device__ __forceinline__ void compute_chunk(uint32_t sA, uint32_t sB,
                                              int aRow0, int aKb, int bRow0, int bKb,
                                              float (&acc)[2][8][4]) {
#pragma unroll
    for (int ks = 0; ks < 4; ks++) {
        uint32_t a[2][4], b[8][2];
#pragma unroll
        for (int im = 0; im < 2; im++) {
            uint32_t byte = (uint32_t)((aRow0 + im * 16) * 128 + ks * 32 + aKb);
            ldsm4(a[im], sA + swz(byte));
        }
#pragma unroll
        for (int g = 0; g < 4; g++) {
            uint32_t byte = (uint32_t)((bRow0 + g * 16) * 128 + ks * 32 + bKb);
            uint32_t r[4];
            ldsm4(r, sB + swz(byte));
            b[2 * g][0] = r[0]; b[2 * g][1] = r[1];
            b[2 * g + 1][0] = r[2]; b[2 * g + 1][1] = r[3];
        }
#pragma unroll
        for (int im = 0; im < 2; im++)
#pragma unroll
            for (int jn = 0; jn < 8; jn++)
                mma16816(acc[im][jn], a[im], b[jn]);
    }
}

__global__ __launch_bounds__(256, 1) void fused_mma_k(
    const bf16* __restrict__ A1h, const bf16* __restrict__ A1l,
    const bf16* __restrict__ B1h, const bf16* __restrict__ B1l, int D1,
    const bf16* __restrict__ A2h, const bf16* __restrict__ A2l,
    const bf16* __restrict__ B2h, const bf16* __restrict__ B2l, int D2) {
    extern __shared__ char dsm[];
    __shared__ float s_wsum[8];

    const int tid  = threadIdx.x;
    const int wid  = tid >> 5;
    const int lane = tid & 31;
    const int wm = wid & 3;          // 4 warps along M (32 rows each)
    const int wn = wid >> 2;         // 2 warps along N (64 cols each)
    const int rowBase = blockIdx.y * TILE_M;
    const int colBase = blockIdx.x * TILE_N;

    uint32_t smem0 = (smem_u32(dsm) + 127u) & ~127u;

    // ldmatrix per-lane address components
    const int aRow0 = wm * 32 + (lane & 15);
    const int aKb   = (lane >> 4) * 16;
    const int bRow0 = wn * 64 + (lane & 7) + ((lane >> 4) << 3);
    const int bKb   = ((lane >> 3) & 1) * 16;

    float acc1[2][8][4], acc2[2][8][4];
#pragma unroll
    for (int im = 0; im < 2; im++)
#pragma unroll
        for (int jn = 0; jn < 8; jn++)
#pragma unroll
            for (int e = 0; e < 4; e++) { acc1[im][jn][e] = 0.f; acc2[im][jn][e] = 0.f; }

    const int C1 = D1 >> 6, C2 = D2 >> 6;
    const int n1 = 3 * C1;
    const int n  = 3 * (C1 + C2);

    for (int i = 0; i < PRE; i++) {
        ChunkArgs ca = resolve(i, n1, C1, C2, A1h, A1l, B1h, B1l, D1, A2h, A2l, B2h, B2l, D2);
        load_chunk(smem0 + (uint32_t)(i & 3) * ST_BYTES, ca.A, ca.Bp, ca.D,
                   rowBase, colBase, ca.c, tid);
        CP_COMMIT();
    }

    for (int i = 0; i < n; i++) {
        if (i < n - 2)       { CP_WAIT(2); }
        else if (i == n - 2) { CP_WAIT(1); }
        else                 { CP_WAIT(0); }
        __syncthreads();

        // prefetch chunk i+PRE into the stage freed by chunk i-1 (safe after the barrier)
        int j = i + PRE;
        if (j < n) {
            ChunkArgs ca = resolve(j, n1, C1, C2, A1h, A1l, B1h, B1l, D1, A2h, A2l, B2h, B2l, D2);
            load_chunk(smem0 + (uint32_t)(j & 3) * ST_BYTES, ca.A, ca.Bp, ca.D,
                       rowBase, colBase, ca.c, tid);
            CP_COMMIT();
        }

        uint32_t sA = smem0 + (uint32_t)(i & 3) * ST_BYTES;
        if (i < n1) compute_chunk(sA, sA + SMB_OFF, aRow0, aKb, bRow0, bKb, acc1);
        else        compute_chunk(sA, sA + SMB_OFF, aRow0, aKb, bRow0, bKb, acc2);
    }

    // epilogue: softplus(saliency * intra) over the register tile
    float local = 0.f;
#pragma unroll
    for (int im = 0; im < 2; im++)
#pragma unroll
        for (int jn = 0; jn < 8; jn++)
#pragma unroll
            for (int e = 0; e < 4; e++) {
                float x  = acc1[im][jn][e];
                float cr = acc2[im][jn][e];
                float sal = 0.3f * cr * cr + 0.7f * x * x;
                float z = sal * x;
                local += fmaxf(z, 0.f) + __logf(1.f + __expf(-fabsf(z)));
            }

#pragma unroll
    for (int off = 16; off; off >>= 1)
        local += __shfl_xor_sync(0xffffffffu, local, off);
    if (lane == 0) s_wsum[wid] = local;
    __syncthreads();
    if (tid == 0) {
        double v = 0.0;
#pragma unroll
        for (int w = 0; w < 8; w++) v += (double)s_wsum[w];
        atomicAdd(&g_acc, v);
    }
}

// ---------------------------------------------------------------------------
extern "C" void kernel_launch(void* const* d_in, const int* in_sizes, int n_in,
                              void* d_out, int out_size) {
    const float* fv  = (const float*)d_in[0];
    const float* fa  = (const float*)d_in[1];
    const float* pv  = (const float*)d_in[2];
    const float* pa  = (const float*)d_in[3];
    const float* Wav = (const float*)d_in[4];
    const float* Wva = (const float*)d_in[5];
    float* out = (float*)d_out;

    bf16 *fvh, *fvl, *fah, *fal, *svh, *svl, *sah, *sal;
    bf16 *pvh, *pvl, *pah, *pal, *pevh, *pevl, *peah, *peal;
    cudaGetSymbolAddress((void**)&fvh, g_fvh);  cudaGetSymbolAddress((void**)&fvl, g_fvl);
    cudaGetSymbolAddress((void**)&fah, g_fah);  cudaGetSymbolAddress((void**)&fal, g_fal);
    cudaGetSymbolAddress((void**)&svh, g_svh);  cudaGetSymbolAddress((void**)&svl, g_svl);
    cudaGetSymbolAddress((void**)&sah, g_sah);  cudaGetSymbolAddress((void**)&sal, g_sal);
    cudaGetSymbolAddress((void**)&pvh, g_pvh);  cudaGetSymbolAddress((void**)&pvl, g_pvl);
    cudaGetSymbolAddress((void**)&pah, g_pah);  cudaGetSymbolAddress((void**)&pal, g_pal);
    cudaGetSymbolAddress((void**)&pevh, g_pevh); cudaGetSymbolAddress((void**)&pevl, g_pevl);
    cudaGetSymbolAddress((void**)&peah, g_peah); cudaGetSymbolAddress((void**)&peal, g_peal);

    zero_acc_k<<<1, 1>>>();

    {
        int tot = M_ * (DV_ / 4);
        prep_feat_k<<<(tot + 255) / 256, 256>>>((const float4*)fv, fvh, fvl, svh, svl, DV_ / 4, tot);
    }
    {
        int tot = M_ * (DA_ / 4);
        prep_feat_k<<<(tot + 255) / 256, 256>>>((const float4*)fa, fah, fal, sah, sal, DA_ / 4, tot);
    }
    split_k<<<(K_ * DV_ / 4 + 255) / 256, 256>>>((const float4*)pv, pvh, pvl, K_ * DV_ / 4);
    split_k<<<(K_ * DA_ / 4 + 255) / 256, 256>>>((const float4*)pa, pah, pal, K_ * DA_ / 4);

    // P_eff_v (K,DA) = proto_vision @ Wav ; P_eff_a (K,DV) = proto_audio @ Wva
    gemm64_split_k<<<dim3(DA_ / 64, K_ / 64), 256>>>(pv, Wav, pevh, pevl, DA_, DV_);
    gemm64_split_k<<<dim3(DV_ / 64, K_ / 64), 256>>>(pa, Wva, peah, peal, DV_, DA_);

    cudaFuncSetAttribute(fused_mma_k, cudaFuncAttributeMaxDynamicSharedMemorySize, DYN_SMEM);
    dim3 grid(K_ / TILE_N, M_ / TILE_M);
    // vision: intra = fv.proto_v (D=768), cross = smooth(fa).P_eff_v (D=512)
    fused_mma_k<<<grid, 256, DYN_SMEM>>>(fvh, fvl, pvh, pvl, DV_, sah, sal, pevh, pevl, DA_);
    // audio:  intra = fa.proto_a (D=512), cross = smooth(fv).P_eff_a (D=768)
    fused_mma_k<<<grid, 256, DYN_SMEM>>>(fah, fal, pah, pal, DA_, svh, svl, peah, peal, DV_);

    final_k<<<1, 1>>>(out);
}

// round 5
// speedup vs baseline: 5.0387x; 2.4016x over previous
#include <cuda_runtime.h>
#include <cuda_fp16.h>
#include <cstdint>

#define B_  8
#define S_  2048
#define DV_ 768
#define DA_ 512
#define K_  512
#define M_  (B_*S_)   // 16384

#define TILE_M 128
#define TILE_N 128
#define KC 64
#define NST 4
#define PRE 3
#define SMB_OFF (TILE_M*KC*2)                 // 16384
#define ST_BYTES (TILE_M*KC*2 + TILE_N*KC*2)  // 32768
#define DYN_SMEM (NST*ST_BYTES + 256)

// ---- scratch (__device__ globals; alloc-guard-safe) ----
__device__ __align__(1024) __half g_fvh[M_*DV_];   // feat_vision fp16
__device__ __align__(1024) __half g_fah[M_*DA_];   // feat_audio fp16
__device__ __align__(1024) __half g_svh[M_*DV_];   // smoothed vision fp16
__device__ __align__(1024) __half g_sah[M_*DA_];   // smoothed audio fp16
__device__ __align__(1024) __half g_pvh[K_*DV_];   // proto_vision fp16
__device__ __align__(1024) __half g_pah[K_*DA_];   // proto_audio fp16
__device__ __align__(1024) __half g_pevh[K_*DA_];  // proto_v @ Wav fp16
__device__ __align__(1024) __half g_peah[K_*DV_];  // proto_a @ Wva fp16
__device__ double g_acc;

__global__ void zero_acc_k() { g_acc = 0.0; }
__global__ void final_k(float* __restrict__ out) { out[0] = (float)(-g_acc); }

// ---------------- low-level helpers ----------------
__device__ __forceinline__ uint32_t smem_u32(const void* p) {
    uint32_t a;
    asm("{ .reg .u64 t; cvta.to.shared.u64 t, %1; cvt.u32.u64 %0, t; }" : "=r"(a) : "l"(p));
    return a;
}
__device__ __forceinline__ uint32_t swz(uint32_t o) { return o ^ ((o >> 3) & 0x70u); }

__device__ __forceinline__ void cpa16(uint32_t d, const void* s) {
    asm volatile("cp.async.cg.shared.global [%0], [%1], 16;" :: "r"(d), "l"(s));
}
#define CP_COMMIT() asm volatile("cp.async.commit_group;" ::: "memory")
#define CP_WAIT(n)  asm volatile("cp.async.wait_group %0;" :: "n"(n) : "memory")

__device__ __forceinline__ void ldsm4(uint32_t* r, uint32_t addr) {
    asm volatile("ldmatrix.sync.aligned.m8n8.x4.shared.b16 {%0,%1,%2,%3}, [%4];"
        : "=r"(r[0]), "=r"(r[1]), "=r"(r[2]), "=r"(r[3]) : "r"(addr));
}
__device__ __forceinline__ void mma16816(float* d, const uint32_t* a, const uint32_t* b) {
    asm volatile("mma.sync.aligned.m16n8k16.row.col.f32.f16.f16.f32 "
        "{%0,%1,%2,%3}, {%4,%5,%6,%7}, {%8,%9}, {%0,%1,%2,%3};"
        : "+f"(d[0]), "+f"(d[1]), "+f"(d[2]), "+f"(d[3])
        : "r"(a[0]), "r"(a[1]), "r"(a[2]), "r"(a[3]), "r"(b[0]), "r"(b[1]));
}

// ---------------- prologue kernels ----------------
__device__ __forceinline__ void cvt4(float4 v, __half* __restrict__ H, size_t idx4) {
    __half2* Hp = reinterpret_cast<__half2*>(H + idx4 * 4);
    Hp[0] = __floats2half2_rn(v.x, v.y);
    Hp[1] = __floats2half2_rn(v.z, v.w);
}

// raw fp16 convert + window-3 temporal mean + fp16 convert, one pass
__global__ void prep_feat_k(const float4* __restrict__ f,
                            __half* __restrict__ fh, __half* __restrict__ sh,
                            int D4, int total) {
    int idx = blockIdx.x * blockDim.x + threadIdx.x;
    if (idx >= total) return;
    int t = (idx / D4) % S_;
    float4 c = f[idx];
    float4 sm = c;
    float cnt = 1.f;
    if (t > 0)      { float4 p = f[idx - D4]; sm.x += p.x; sm.y += p.y; sm.z += p.z; sm.w += p.w; cnt += 1.f; }
    if (t < S_ - 1) { float4 n = f[idx + D4]; sm.x += n.x; sm.y += n.y; sm.z += n.z; sm.w += n.w; cnt += 1.f; }
    float inv = 1.f / cnt;
    sm.x *= inv; sm.y *= inv; sm.z *= inv; sm.w *= inv;
    cvt4(c, fh, idx);
    cvt4(sm, sh, idx);
}

__global__ void cvt_k(const float4* __restrict__ x, __half* __restrict__ h, int n4) {
    int idx = blockIdx.x * blockDim.x + threadIdx.x;
    if (idx >= n4) return;
    cvt4(x[idx], h, idx);
}

// P_eff = A(K_,Kd) @ W(Kd,N) in fp32, output fp16
__global__ __launch_bounds__(256) void gemm64_k(
    const float* __restrict__ A, const float* __restrict__ W,
    __half* __restrict__ Oh, int N, int Kd) {
    __shared__ float As[16][68];
    __shared__ float Ws[16][68];
    int tid = threadIdx.x;
    int tx = tid & 15, ty = tid >> 4;
    int row0 = blockIdx.y * 64, col0 = blockIdx.x * 64;
    float acc[4][4] = {};
    for (int kt = 0; kt < Kd; kt += 16) {
#pragma unroll
        for (int i = 0; i < 4; i++) {
            int e = tid + i * 256;
            As[e & 15][e >> 4] = A[(size_t)(row0 + (e >> 4)) * Kd + kt + (e & 15)];
        }
#pragma unroll
        for (int i = 0; i < 4; i++) {
            int e = tid + i * 256;
            Ws[e >> 6][e & 63] = W[(size_t)(kt + (e >> 6)) * N + col0 + (e & 63)];
        }
        __syncthreads();
#pragma unroll
        for (int kk = 0; kk < 16; kk++) {
            float a[4], b[4];
#pragma unroll
            for (int i = 0; i < 4; i++) a[i] = As[kk][ty * 4 + i];
#pragma unroll
            for (int j = 0; j < 4; j++) b[j] = Ws[kk][tx * 4 + j];
#pragma unroll
            for (int i = 0; i < 4; i++)
#pragma unroll
                for (int j = 0; j < 4; j++) acc[i][j] += a[i] * b[j];
        }
        __syncthreads();
    }
#pragma unroll
    for (int i = 0; i < 4; i++)
#pragma unroll
        for (int j = 0; j < 4; j++)
            Oh[(size_t)(row0 + ty * 4 + i) * N + col0 + tx * 4 + j] =
                __float2half_rn(acc[i][j]);
}

// ---------------- fused dual-GEMM (mma.sync fp16) + energy ----------------
struct ModParams {
    const __half* A1; const __half* B1; int D1;   // intra: feat . proto
    const __half* A2; const __half* B2; int D2;   // cross: smooth(comp) . P_eff
};

__device__ __forceinline__ void load_chunk(uint32_t st, const __half* Ap, const __half* Bp,
                                           int D, int rowBase, int colBase, int c, int tid) {
#pragma unroll
    for (int i = 0; i < 4; i++) {
        int e = tid + i * 256;
        int r = e >> 3, cg = e & 7;
        cpa16(st + swz((uint32_t)(r * 128 + cg * 16)),
              Ap + (size_t)(rowBase + r) * D + (c << 6) + cg * 8);
    }
    uint32_t sB = st + SMB_OFF;
#pragma unroll
    for (int i = 0; i < 4; i++) {
        int e = tid + i * 256;
        int r = e >> 3, cg = e & 7;
        cpa16(sB + swz((uint32_t)(r * 128 + cg * 16)),
              Bp + (size_t)(colBase + r) * D + (c << 6) + cg * 8);
    }
}

__device__ __forceinline__ void compute_chunk(uint32_t sA, uint32_t sB,
                                              int aRow0, int aKb, int bRow0, int bKb,
                                              float (&acc)[2][8][4]) {
#pragma unroll
    for (int ks = 0; ks < 4; ks++) {
        uint32_t a[2][4], b[8][2];
#pragma unroll
        for (int im = 0; im < 2; im++) {
            uint32_t byte = (uint32_t)((aRow0 + im * 16) * 128 + ks * 32 + aKb);
            ldsm4(a[im], sA + swz(byte));
        }
#pragma unroll
        for (int g = 0; g < 4; g++) {
            uint32_t byte = (uint32_t)((bRow0 + g * 16) * 128 + ks * 32 + bKb);
            uint32_t r[4];
            ldsm4(r, sB + swz(byte));
            b[2 * g][0] = r[0]; b[2 * g][1] = r[1];
            b[2 * g + 1][0] = r[2]; b[2 * g + 1][1] = r[3];
        }
#pragma unroll
        for (int im = 0; im < 2; im++)
#pragma unroll
            for (int jn = 0; jn < 8; jn++)
                mma16816(acc[im][jn], a[im], b[jn]);
    }
}

__global__ __launch_bounds__(256, 1) void fused_mma_k(ModParams Pv, ModParams Pa) {
    extern __shared__ char dsm[];
    __shared__ float s_wsum[8];

    const ModParams P = blockIdx.z ? Pa : Pv;

    const int tid  = threadIdx.x;
    const int wid  = tid >> 5;
    const int lane = tid & 31;
    const int wm = wid & 3;
    const int wn = wid >> 2;
    const int rowBase = blockIdx.y * TILE_M;
    const int colBase = blockIdx.x * TILE_N;

    uint32_t smem0 = (smem_u32(dsm) + 127u) & ~127u;

    const int aRow0 = wm * 32 + (lane & 15);
    const int aKb   = (lane >> 4) * 16;
    const int bRow0 = wn * 64 + (lane & 7) + ((lane >> 4) << 3);
    const int bKb   = ((lane >> 3) & 1) * 16;

    float acc1[2][8][4], acc2[2][8][4];
#pragma unroll
    for (int im = 0; im < 2; im++)
#pragma unroll
        for (int jn = 0; jn < 8; jn++)
#pragma unroll
            for (int e = 0; e < 4; e++) { acc1[im][jn][e] = 0.f; acc2[im][jn][e] = 0.f; }

    const int C1 = P.D1 >> 6;
    const int C2 = P.D2 >> 6;
    const int n  = C1 + C2;

    for (int i = 0; i < PRE; i++) {
        int m2 = (i >= C1);
        load_chunk(smem0 + (uint32_t)(i & 3) * ST_BYTES,
                   m2 ? P.A2 : P.A1, m2 ? P.B2 : P.B1, m2 ? P.D2 : P.D1,
                   rowBase, colBase, m2 ? i - C1 : i, tid);
        CP_COMMIT();
    }

    for (int i = 0; i < n; i++) {
        if (i < n - 2)       { CP_WAIT(2); }
        else if (i == n - 2) { CP_WAIT(1); }
        else                 { CP_WAIT(0); }
        __syncthreads();

        int j = i + PRE;
        if (j < n) {
            int m2 = (j >= C1);
            load_chunk(smem0 + (uint32_t)(j & 3) * ST_BYTES,
                       m2 ? P.A2 : P.A1, m2 ? P.B2 : P.B1, m2 ? P.D2 : P.D1,
                       rowBase, colBase, m2 ? j - C1 : j, tid);
            CP_COMMIT();
        }

        uint32_t sA = smem0 + (uint32_t)(i & 3) * ST_BYTES;
        if (i < C1) compute_chunk(sA, sA + SMB_OFF, aRow0, aKb, bRow0, bKb, acc1);
        else        compute_chunk(sA, sA + SMB_OFF, aRow0, aKb, bRow0, bKb, acc2);
    }

    // epilogue: softplus(saliency * intra)
    float local = 0.f;
#pragma unroll
    for (int im = 0; im < 2; im++)
#pragma unroll
        for (int jn = 0; jn < 8; jn++)
#pragma unroll
            for (int e = 0; e < 4; e++) {
                float x  = acc1[im][jn][e];
                float cr = acc2[im][jn][e];
                float sal = 0.3f * cr * cr + 0.7f * x * x;
                float z = sal * x;
                local += fmaxf(z, 0.f) + __logf(1.f + __expf(-fabsf(z)));
            }

#pragma unroll
    for (int off = 16; off; off >>= 1)
        local += __shfl_xor_sync(0xffffffffu, local, off);
    if (lane == 0) s_wsum[wid] = local;
    __syncthreads();
    if (tid == 0) {
        double v = 0.0;
#pragma unroll
        for (int w = 0; w < 8; w++) v += (double)s_wsum[w];
        atomicAdd(&g_acc, v);
    }
}

// ---------------------------------------------------------------------------
extern "C" void kernel_launch(void* const* d_in, const int* in_sizes, int n_in,
                              void* d_out, int out_size) {
    const float* fv  = (const float*)d_in[0];
    const float* fa  = (const float*)d_in[1];
    const float* pv  = (const float*)d_in[2];
    const float* pa  = (const float*)d_in[3];
    const float* Wav = (const float*)d_in[4];
    const float* Wva = (const float*)d_in[5];
    float* out = (float*)d_out;

    __half *fvh, *fah, *svh, *sah, *pvh, *pah, *pevh, *peah;
    cudaGetSymbolAddress((void**)&fvh, g_fvh);
    cudaGetSymbolAddress((void**)&fah, g_fah);
    cudaGetSymbolAddress((void**)&svh, g_svh);
    cudaGetSymbolAddress((void**)&sah, g_sah);
    cudaGetSymbolAddress((void**)&pvh, g_pvh);
    cudaGetSymbolAddress((void**)&pah, g_pah);
    cudaGetSymbolAddress((void**)&pevh, g_pevh);
    cudaGetSymbolAddress((void**)&peah, g_peah);

    zero_acc_k<<<1, 1>>>();

    {
        int tot = M_ * (DV_ / 4);
        prep_feat_k<<<(tot + 255) / 256, 256>>>((const float4*)fv, fvh, svh, DV_ / 4, tot);
    }
    {
        int tot = M_ * (DA_ / 4);
        prep_feat_k<<<(tot + 255) / 256, 256>>>((const float4*)fa, fah, sah, DA_ / 4, tot);
    }
    cvt_k<<<(K_ * DV_ / 4 + 255) / 256, 256>>>((const float4*)pv, pvh, K_ * DV_ / 4);
    cvt_k<<<(K_ * DA_ / 4 + 255) / 256, 256>>>((const float4*)pa, pah, K_ * DA_ / 4);

    // P_eff_v (K,DA) = proto_vision @ Wav ; P_eff_a (K,DV) = proto_audio @ Wva
    gemm64_k<<<dim3(DA_ / 64, K_ / 64), 256>>>(pv, Wav, pevh, DA_, DV_);
    gemm64_k<<<dim3(DV_ / 64, K_ / 64), 256>>>(pa, Wva, peah, DV_, DA_);

    ModParams Pv { fvh, pvh, DV_, sah, pevh, DA_ };   // vision energy
    ModParams Pa { fah, pah, DA_, svh, peah, DV_ };   // audio energy

    cudaFuncSetAttribute(fused_mma_k, cudaFuncAttributeMaxDynamicSharedMemorySize, DYN_SMEM);
    dim3 grid(K_ / TILE_N, M_ / TILE_M, 2);
    fused_mma_k<<<grid, 256, DYN_SMEM>>>(Pv, Pa);

    final_k<<<1, 1>>>(out);
}

// round 6
// speedup vs baseline: 7.3046x; 1.4497x over previous
#include <cuda_runtime.h>
#include <cuda_fp16.h>
#include <cstdint>

#define B_  8
#define S_  2048
#define DV_ 768
#define DA_ 512
#define K_  512
#define M_  (B_*S_)   // 16384

#define TILE_M 128
#define TILE_N 128
#define KC 64
#define NST 5
#define PRE 4
#define SMB_OFF (TILE_M*KC*2)                 // 16384
#define ST_BYTES (TILE_M*KC*2 + TILE_N*KC*2)  // 32768
#define DYN_SMEM (NST*ST_BYTES + 256)
#define PEFF_NST 4
#define PEFF_SMEM (PEFF_NST*ST_BYTES + 256)

// ---- scratch (__device__ globals; alloc-guard-safe) ----
__device__ __align__(1024) __half g_fvh[M_*DV_];
__device__ __align__(1024) __half g_fah[M_*DA_];
__device__ __align__(1024) __half g_svh[M_*DV_];
__device__ __align__(1024) __half g_sah[M_*DA_];
__device__ __align__(1024) __half g_pvh[K_*DV_];
__device__ __align__(1024) __half g_pah[K_*DA_];
__device__ __align__(1024) __half g_pevh[K_*DA_];
__device__ __align__(1024) __half g_peah[K_*DV_];
__device__ __align__(1024) __half g_wtav[DA_*DV_];  // Wav^T : (DA, DV)
__device__ __align__(1024) __half g_wtva[DV_*DA_];  // Wva^T : (DV, DA)
__device__ double g_acc;

__global__ void zero_acc_k() { g_acc = 0.0; }
__global__ void final_k(float* __restrict__ out) { out[0] = (float)(-g_acc); }

// ---------------- low-level helpers ----------------
__device__ __forceinline__ uint32_t smem_u32(const void* p) {
    uint32_t a;
    asm("{ .reg .u64 t; cvta.to.shared.u64 t, %1; cvt.u32.u64 %0, t; }" : "=r"(a) : "l"(p));
    return a;
}
__device__ __forceinline__ uint32_t swz(uint32_t o) { return o ^ ((o >> 3) & 0x70u); }

__device__ __forceinline__ void cpa16(uint32_t d, const void* s) {
    asm volatile("cp.async.cg.shared.global [%0], [%1], 16;" :: "r"(d), "l"(s));
}
#define CP_COMMIT() asm volatile("cp.async.commit_group;" ::: "memory")
#define CP_WAIT(n)  asm volatile("cp.async.wait_group %0;" :: "n"(n) : "memory")

__device__ __forceinline__ void ldsm4(uint32_t* r, uint32_t addr) {
    asm volatile("ldmatrix.sync.aligned.m8n8.x4.shared.b16 {%0,%1,%2,%3}, [%4];"
        : "=r"(r[0]), "=r"(r[1]), "=r"(r[2]), "=r"(r[3]) : "r"(addr));
}
__device__ __forceinline__ void mma16816(float* d, const uint32_t* a, const uint32_t* b) {
    asm volatile("mma.sync.aligned.m16n8k16.row.col.f32.f16.f16.f32 "
        "{%0,%1,%2,%3}, {%4,%5,%6,%7}, {%8,%9}, {%0,%1,%2,%3};"
        : "+f"(d[0]), "+f"(d[1]), "+f"(d[2]), "+f"(d[3])
        : "r"(a[0]), "r"(a[1]), "r"(a[2]), "r"(a[3]), "r"(b[0]), "r"(b[1]));
}

// ---------------- prologue kernels ----------------
__device__ __forceinline__ void cvt4(float4 v, __half* __restrict__ H, size_t idx4) {
    __half2* Hp = reinterpret_cast<__half2*>(H + idx4 * 4);
    Hp[0] = __floats2half2_rn(v.x, v.y);
    Hp[1] = __floats2half2_rn(v.z, v.w);
}

__device__ __forceinline__ void prep_one(const float4* __restrict__ f,
                                         __half* __restrict__ fh, __half* __restrict__ sh,
                                         int D4, int idx) {
    int t = (idx / D4) % S_;
    float4 c = f[idx];
    float4 sm = c;
    float cnt = 1.f;
    if (t > 0)      { float4 p = f[idx - D4]; sm.x += p.x; sm.y += p.y; sm.z += p.z; sm.w += p.w; cnt += 1.f; }
    if (t < S_ - 1) { float4 n = f[idx + D4]; sm.x += n.x; sm.y += n.y; sm.z += n.z; sm.w += n.w; cnt += 1.f; }
    float inv = 1.f / cnt;
    sm.x *= inv; sm.y *= inv; sm.z *= inv; sm.w *= inv;
    cvt4(c, fh, idx);
    cvt4(sm, sh, idx);
}

// both modalities: fp16 convert + window-3 smooth + fp16 convert, one launch
__global__ void prep2_k(const float4* __restrict__ fv, __half* __restrict__ fvh,
                        __half* __restrict__ svh,
                        const float4* __restrict__ fa, __half* __restrict__ fah,
                        __half* __restrict__ sah) {
    const int totv = M_ * (DV_ / 4);
    const int tota = M_ * (DA_ / 4);
    int idx = blockIdx.x * blockDim.x + threadIdx.x;
    if (idx < totv)               prep_one(fv, fvh, svh, DV_ / 4, idx);
    else if (idx < totv + tota)   prep_one(fa, fah, sah, DA_ / 4, idx - totv);
}

// both protos fp16 convert, one launch
__global__ void cvt2_k(const float4* __restrict__ xv, __half* __restrict__ hv, int n4v,
                       const float4* __restrict__ xa, __half* __restrict__ ha, int n4a) {
    int idx = blockIdx.x * blockDim.x + threadIdx.x;
    if (idx < n4v)             cvt4(xv[idx], hv, idx);
    else if (idx < n4v + n4a)  cvt4(xa[idx - n4v], ha, idx - n4v);
}

// W (R, C) fp32 -> Wt (C, R) fp16
__global__ void transcvt_k(const float* __restrict__ W, __half* __restrict__ Wt,
                           int R, int C) {
    __shared__ float t[32][33];
    int tx = threadIdx.x, ty = threadIdx.y;   // (32, 8)
    int d0 = blockIdx.x * 32, n0 = blockIdx.y * 32;
#pragma unroll
    for (int j = 0; j < 4; j++)
        t[ty + 8 * j][tx] = W[(size_t)(d0 + ty + 8 * j) * C + n0 + tx];
    __syncthreads();
#pragma unroll
    for (int j = 0; j < 4; j++)
        Wt[(size_t)(n0 + ty + 8 * j) * R + d0 + tx] = __float2half_rn(t[tx][ty + 8 * j]);
}

// ---------------- shared GEMM building blocks ----------------
__device__ __forceinline__ void load_chunk(uint32_t st, const __half* Ap, const __half* Bp,
                                           int D, int rowBase, int colBase, int c, int tid) {
#pragma unroll
    for (int i = 0; i < 4; i++) {
        int e = tid + i * 256;
        int r = e >> 3, cg = e & 7;
        cpa16(st + swz((uint32_t)(r * 128 + cg * 16)),
              Ap + (size_t)(rowBase + r) * D + (c << 6) + cg * 8);
    }
    uint32_t sB = st + SMB_OFF;
#pragma unroll
    for (int i = 0; i < 4; i++) {
        int e = tid + i * 256;
        int r = e >> 3, cg = e & 7;
        cpa16(sB + swz((uint32_t)(r * 128 + cg * 16)),
              Bp + (size_t)(colBase + r) * D + (c << 6) + cg * 8);
    }
}

__device__ __forceinline__ void compute_chunk(uint32_t sA, uint32_t sB,
                                              int aRow0, int aKb, int bRow0, int bKb,
                                              float (&acc)[2][8][4]) {
#pragma unroll
    for (int ks = 0; ks < 4; ks++) {
        uint32_t a[2][4], b[8][2];
#pragma unroll
        for (int im = 0; im < 2; im++) {
            uint32_t byte = (uint32_t)((aRow0 + im * 16) * 128 + ks * 32 + aKb);
            ldsm4(a[im], sA + swz(byte));
        }
#pragma unroll
        for (int g = 0; g < 4; g++) {
            uint32_t byte = (uint32_t)((bRow0 + g * 16) * 128 + ks * 32 + bKb);
            uint32_t r[4];
            ldsm4(r, sB + swz(byte));
            b[2 * g][0] = r[0]; b[2 * g][1] = r[1];
            b[2 * g + 1][0] = r[2]; b[2 * g + 1][1] = r[3];
        }
#pragma unroll
        for (int im = 0; im < 2; im++)
#pragma unroll
            for (int jn = 0; jn < 8; jn++)
                mma16816(acc[im][jn], a[im], b[jn]);
    }
}

// ---------------- P_eff GEMM: O(512, N) = A(512, D) @ Bt(N, D)^T, fp16 out ----------------
__global__ __launch_bounds__(256, 1) void peff_mma_k(
    const __half* __restrict__ Av, const __half* __restrict__ Btv,
    __half* __restrict__ Ov, int Dv, int Nv,
    const __half* __restrict__ Aa, const __half* __restrict__ Bta,
    __half* __restrict__ Oa, int Da, int Na) {
    extern __shared__ char dsm[];

    const __half* A  = blockIdx.z ? Aa  : Av;
    const __half* Bt = blockIdx.z ? Bta : Btv;
    __half* O = blockIdx.z ? Oa : Ov;
    const int D = blockIdx.z ? Da : Dv;
    const int N = blockIdx.z ? Na : Nv;
    if ((int)blockIdx.x * TILE_N >= N) return;

    const int tid  = threadIdx.x;
    const int wid  = tid >> 5;
    const int lane = tid & 31;
    const int wm = wid & 3;
    const int wn = wid >> 2;
    const int rowBase = blockIdx.y * TILE_M;
    const int colBase = blockIdx.x * TILE_N;

    uint32_t smem0 = (smem_u32(dsm) + 127u) & ~127u;

    const int aRow0 = wm * 32 + (lane & 15);
    const int aKb   = (lane >> 4) * 16;
    const int bRow0 = wn * 64 + (lane & 7) + ((lane >> 4) << 3);
    const int bKb   = ((lane >> 3) & 1) * 16;

    float acc[2][8][4];
#pragma unroll
    for (int im = 0; im < 2; im++)
#pragma unroll
        for (int jn = 0; jn < 8; jn++)
#pragma unroll
            for (int e = 0; e < 4; e++) acc[im][jn][e] = 0.f;

    const int n = D >> 6;
    for (int i = 0; i < 3; i++) {
        load_chunk(smem0 + (uint32_t)(i & 3) * ST_BYTES, A, Bt, D, rowBase, colBase, i, tid);
        CP_COMMIT();
    }
    for (int i = 0; i < n; i++) {
        int w = n - 1 - i;
        if (w >= 2)      { CP_WAIT(2); }
        else if (w == 1) { CP_WAIT(1); }
        else             { CP_WAIT(0); }
        __syncthreads();
        int j = i + 3;
        if (j < n) {
            load_chunk(smem0 + (uint32_t)(j & 3) * ST_BYTES, A, Bt, D, rowBase, colBase, j, tid);
            CP_COMMIT();
        }
        uint32_t sA = smem0 + (uint32_t)(i & 3) * ST_BYTES;
        compute_chunk(sA, sA + SMB_OFF, aRow0, aKb, bRow0, bKb, acc);
    }

    // store fp16 (standard m16n8 C fragment layout)
    const int r0 = rowBase + wm * 32 + (lane >> 2);
    const int c0 = colBase + wn * 64 + (lane & 3) * 2;
#pragma unroll
    for (int im = 0; im < 2; im++)
#pragma unroll
        for (int jn = 0; jn < 8; jn++) {
            int r = r0 + im * 16;
            int c = c0 + jn * 8;
            *reinterpret_cast<__half2*>(O + (size_t)r * N + c) =
                __floats2half2_rn(acc[im][jn][0], acc[im][jn][1]);
            *reinterpret_cast<__half2*>(O + (size_t)(r + 8) * N + c) =
                __floats2half2_rn(acc[im][jn][2], acc[im][jn][3]);
        }
}

// ---------------- fused dual-GEMM (mma.sync fp16) + energy ----------------
struct ModParams {
    const __half* A1; const __half* B1; int D1;   // intra: feat . proto
    const __half* A2; const __half* B2; int D2;   // cross: smooth(comp) . P_eff
};

__global__ __launch_bounds__(256, 1) void fused_mma_k(ModParams Pv, ModParams Pa) {
    extern __shared__ char dsm[];
    __shared__ float s_wsum[8];

    const ModParams P = blockIdx.z ? Pa : Pv;

    const int tid  = threadIdx.x;
    const int wid  = tid >> 5;
    const int lane = tid & 31;
    const int wm = wid & 3;
    const int wn = wid >> 2;
    const int rowBase = blockIdx.y * TILE_M;
    const int colBase = blockIdx.x * TILE_N;

    uint32_t smem0 = (smem_u32(dsm) + 127u) & ~127u;

    const int aRow0 = wm * 32 + (lane & 15);
    const int aKb   = (lane >> 4) * 16;
    const int bRow0 = wn * 64 + (lane & 7) + ((lane >> 4) << 3);
    const int bKb   = ((lane >> 3) & 1) * 16;

    float acc1[2][8][4], acc2[2][8][4];
#pragma unroll
    for (int im = 0; im < 2; im++)
#pragma unroll
        for (int jn = 0; jn < 8; jn++)
#pragma unroll
            for (int e = 0; e < 4; e++) { acc1[im][jn][e] = 0.f; acc2[im][jn][e] = 0.f; }

    const int C1 = P.D1 >> 6;
    const int C2 = P.D2 >> 6;
    const int n  = C1 + C2;   // 20

    for (int i = 0; i < PRE; i++) {
        int m2 = (i >= C1);
        load_chunk(smem0 + (uint32_t)(i % NST) * ST_BYTES,
                   m2 ? P.A2 : P.A1, m2 ? P.B2 : P.B1, m2 ? P.D2 : P.D1,
                   rowBase, colBase, m2 ? i - C1 : i, tid);
        CP_COMMIT();
    }

    for (int i = 0; i < n; i++) {
        int w = n - 1 - i;
        if (w >= 3)      { CP_WAIT(3); }
        else if (w == 2) { CP_WAIT(2); }
        else if (w == 1) { CP_WAIT(1); }
        else             { CP_WAIT(0); }
        __syncthreads();

        int j = i + PRE;
        if (j < n) {
            int m2 = (j >= C1);
            load_chunk(smem0 + (uint32_t)(j % NST) * ST_BYTES,
                       m2 ? P.A2 : P.A1, m2 ? P.B2 : P.B1, m2 ? P.D2 : P.D1,
                       rowBase, colBase, m2 ? j - C1 : j, tid);
            CP_COMMIT();
        }

        uint32_t sA = smem0 + (uint32_t)(i % NST) * ST_BYTES;
        if (i < C1) compute_chunk(sA, sA + SMB_OFF, aRow0, aKb, bRow0, bKb, acc1);
        else        compute_chunk(sA, sA + SMB_OFF, aRow0, aKb, bRow0, bKb, acc2);
    }

    // epilogue: softplus(saliency * intra)
    float local = 0.f;
#pragma unroll
    for (int im = 0; im < 2; im++)
#pragma unroll
        for (int jn = 0; jn < 8; jn++)
#pragma unroll
            for (int e = 0; e < 4; e++) {
                float x  = acc1[im][jn][e];
                float cr = acc2[im][jn][e];
                float sal = 0.3f * cr * cr + 0.7f * x * x;
                float z = sal * x;
                local += fmaxf(z, 0.f) + __logf(1.f + __expf(-fabsf(z)));
            }

#pragma unroll
    for (int off = 16; off; off >>= 1)
        local += __shfl_xor_sync(0xffffffffu, local, off);
    if (lane == 0) s_wsum[wid] = local;
    __syncthreads();
    if (tid == 0) {
        double v = 0.0;
#pragma unroll
        for (int w = 0; w < 8; w++) v += (double)s_wsum[w];
        atomicAdd(&g_acc, v);
    }
}

// ---------------------------------------------------------------------------
extern "C" void kernel_launch(void* const* d_in, const int* in_sizes, int n_in,
                              void* d_out, int out_size) {
    const float* fv  = (const float*)d_in[0];
    const float* fa  = (const float*)d_in[1];
    const float* pv  = (const float*)d_in[2];
    const float* pa  = (const float*)d_in[3];
    const float* Wav = (const float*)d_in[4];
    const float* Wva = (const float*)d_in[5];
    float* out = (float*)d_out;

    __half *fvh, *fah, *svh, *sah, *pvh, *pah, *pevh, *peah, *wtav, *wtva;
    cudaGetSymbolAddress((void**)&fvh, g_fvh);
    cudaGetSymbolAddress((void**)&fah, g_fah);
    cudaGetSymbolAddress((void**)&svh, g_svh);
    cudaGetSymbolAddress((void**)&sah, g_sah);
    cudaGetSymbolAddress((void**)&pvh, g_pvh);
    cudaGetSymbolAddress((void**)&pah, g_pah);
    cudaGetSymbolAddress((void**)&pevh, g_pevh);
    cudaGetSymbolAddress((void**)&peah, g_peah);
    cudaGetSymbolAddress((void**)&wtav, g_wtav);
    cudaGetSymbolAddress((void**)&wtva, g_wtva);

    zero_acc_k<<<1, 1>>>();

    {
        int tot = M_ * (DV_ / 4) + M_ * (DA_ / 4);
        prep2_k<<<(tot + 255) / 256, 256>>>((const float4*)fv, fvh, svh,
                                            (const float4*)fa, fah, sah);
    }
    {
        int n4v = K_ * DV_ / 4, n4a = K_ * DA_ / 4;
        cvt2_k<<<(n4v + n4a + 255) / 256, 256>>>((const float4*)pv, pvh, n4v,
                                                 (const float4*)pa, pah, n4a);
    }
    // Wav (DV, DA) -> wtav (DA, DV) ; Wva (DA, DV) -> wtva (DV, DA)
    transcvt_k<<<dim3(DV_ / 32, DA_ / 32), dim3(32, 8)>>>(Wav, wtav, DV_, DA_);
    transcvt_k<<<dim3(DA_ / 32, DV_ / 32), dim3(32, 8)>>>(Wva, wtva, DA_, DV_);

    // P_eff_v (K, DA) = proto_v @ Wav = pvh(512, 768) . wtav(512, 768)^T
    // P_eff_a (K, DV) = proto_a @ Wva = pah(512, 512) . wtva(768, 512)^T
    cudaFuncSetAttribute(peff_mma_k, cudaFuncAttributeMaxDynamicSharedMemorySize, PEFF_SMEM);
    {
        dim3 g(DV_ / TILE_N, K_ / TILE_M, 2);  // x covers max(Nv, Na)/128 = 6
        peff_mma_k<<<g, 256, PEFF_SMEM>>>(pvh, wtav, pevh, DV_, DA_,
                                          pah, wtva, peah, DA_, DV_);
    }

    ModParams Pv { fvh, pvh, DV_, sah, pevh, DA_ };   // vision energy
    ModParams Pa { fah, pah, DA_, svh, peah, DV_ };   // audio energy

    cudaFuncSetAttribute(fused_mma_k, cudaFuncAttributeMaxDynamicSharedMemorySize, DYN_SMEM);
    dim3 grid(K_ / TILE_N, M_ / TILE_M, 2);
    fused_mma_k<<<grid, 256, DYN_SMEM>>>(Pv, Pa);

    final_k<<<1, 1>>>(out);
}